// round 2
// baseline (speedup 1.0000x reference)
#include <cuda_runtime.h>
#include <cuda_bf16.h>
#include <cstdint>

#define B 2
#define S 2048
#define HIDDEN 896
#define NH 14
#define NKV 2
#define HD 64
#define NREP 7
#define MTOK (B*S)          // 4096 tokens

// ---------------- scratch (device globals; no allocation allowed) ----------------
__device__ float g_qlin[MTOK * HIDDEN];        // 4096 x 896
__device__ float g_klin[MTOK * (NKV*HD)];      // 4096 x 128
__device__ float g_vlin[MTOK * (NKV*HD)];      // 4096 x 128
__device__ float g_q[B * NH * S * HD];         // [b,h,s,d]
__device__ float g_k[B * NKV * S * HD];        // [b,kv,s,d]
__device__ float g_v[B * NKV * S * HD];        // [b,kv,s,d]
__device__ float g_attn[MTOK * HIDDEN];        // [b,s,h*d]

// ---------------- GEMM: C[m,n] = sum_k X[m,k]*W[n,k] + bias[n] ----------------
// X: (M,K) row-major, W: (N,K) row-major. M,N multiples of 64, K multiple of 16.
#define BM 64
#define BN 64
#define BKK 16

__global__ __launch_bounds__(256) void gemm_xwT(const float* __restrict__ X,
                                                const float* __restrict__ W,
                                                const float* __restrict__ bias,
                                                float* __restrict__ C,
                                                int M, int N, int K) {
    __shared__ float Xs[BKK][BM + 2];
    __shared__ float Ws[BKK][BN + 2];

    const int tid = threadIdx.x;
    const int tx = tid & 15;       // n direction
    const int ty = tid >> 4;       // m direction
    const int m0 = blockIdx.y * BM;
    const int n0 = blockIdx.x * BN;

    float acc[4][4];
#pragma unroll
    for (int i = 0; i < 4; i++)
#pragma unroll
        for (int j = 0; j < 4; j++) acc[i][j] = 0.f;

    for (int k0 = 0; k0 < K; k0 += BKK) {
        // load X tile (BM x BKK) transposed into Xs[kk][mm]
#pragma unroll
        for (int i = tid; i < BM * BKK; i += 256) {
            int mm = i >> 4;          // /16
            int kk = i & 15;
            Xs[kk][mm] = X[(size_t)(m0 + mm) * K + k0 + kk];
        }
#pragma unroll
        for (int i = tid; i < BN * BKK; i += 256) {
            int nn = i >> 4;
            int kk = i & 15;
            Ws[kk][nn] = W[(size_t)(n0 + nn) * K + k0 + kk];
        }
        __syncthreads();

#pragma unroll
        for (int kk = 0; kk < BKK; kk++) {
            float xr[4], wr[4];
#pragma unroll
            for (int i = 0; i < 4; i++) xr[i] = Xs[kk][ty * 4 + i];
#pragma unroll
            for (int j = 0; j < 4; j++) wr[j] = Ws[kk][tx * 4 + j];
#pragma unroll
            for (int i = 0; i < 4; i++)
#pragma unroll
                for (int j = 0; j < 4; j++) acc[i][j] += xr[i] * wr[j];
        }
        __syncthreads();
    }

#pragma unroll
    for (int i = 0; i < 4; i++) {
        int m = m0 + ty * 4 + i;
#pragma unroll
        for (int j = 0; j < 4; j++) {
            int n = n0 + tx * 4 + j;
            float bv = bias ? bias[n] : 0.f;
            C[(size_t)m * N + n] = acc[i][j] + bv;
        }
    }
}

// ---------------- RoPE + reshape ----------------
// One thread per (b,s,head,pair). head in [0,14) -> q rope, [14,16) -> k rope, [16,18) -> v copy.
// position_ids in the reference is broadcast(arange(S)) — position == s index.
// (We deliberately do NOT dereference the position buffer: its on-disk dtype is
//  ambiguous between int32/int64 under JAX default x64-disabled config.)
__global__ void rope_reshape(const float* __restrict__ qlin,
                             const float* __restrict__ klin,
                             const float* __restrict__ vlin,
                             float* __restrict__ qout,
                             float* __restrict__ kout,
                             float* __restrict__ vout) {
    int idx = blockIdx.x * blockDim.x + threadIdx.x;
    const int total = B * S * 18 * 32;
    if (idx >= total) return;
    int pair = idx & 31;
    int rest = idx >> 5;
    int head = rest % 18;
    int bs = rest / 18;
    int b = bs / S, s = bs % S;

    if (head >= 16) {
        // v copy: [b,s,kv,d] -> [b,kv,s,d]
        int kvh = head - 16;
        const float* src = vlin + (size_t)bs * (NKV * HD) + kvh * HD;
        float* dst = vout + (((size_t)b * NKV + kvh) * S + s) * HD;
        dst[pair] = src[pair];
        dst[pair + 32] = src[pair + 32];
        return;
    }

    float pos = (float)s;
    // inv_freq[i] = theta^{-i/32} = 2^{-i*log2(1e6)/32}
    const float LOG2_THETA_OVER_32 = 0.62286105580517513f;  // log2(1e6)/32
    float inv = exp2f(-(float)pair * LOG2_THETA_OVER_32);
    float f = pos * inv;
    float sn, cs;
    sincosf(f, &sn, &cs);

    if (head < 14) {
        const float* src = qlin + (size_t)bs * HIDDEN + head * HD;
        float x1 = src[pair], x2 = src[pair + 32];
        float* dst = qout + (((size_t)b * NH + head) * S + s) * HD;
        dst[pair] = x1 * cs - x2 * sn;
        dst[pair + 32] = x2 * cs + x1 * sn;
    } else {
        int kvh = head - 14;
        const float* src = klin + (size_t)bs * (NKV * HD) + kvh * HD;
        float x1 = src[pair], x2 = src[pair + 32];
        float* dst = kout + (((size_t)b * NKV + kvh) * S + s) * HD;
        dst[pair] = x1 * cs - x2 * sn;
        dst[pair + 32] = x2 * cs + x1 * sn;
    }
}

// ---------------- Flash attention (causal, GQA) ----------------
// grid: (S/64, NH, B), block: 256 threads (8 warps). Each warp owns 8 query rows.
// Dynamic smem: Qs[64*64] | Ks[64*65] | Vs[64*64] | Ps[64*64]
#define ATTN_SMEM ((64*64 + 64*65 + 64*64 + 64*64) * (int)sizeof(float))

__global__ __launch_bounds__(256) void attn_kernel(const float* __restrict__ Q,
                                                   const float* __restrict__ K,
                                                   const float* __restrict__ V,
                                                   float* __restrict__ O) {
    extern __shared__ float sm[];
    float* Qs = sm;                 // 64*64, row-major [q][d]
    float* Ks = sm + 64 * 64;       // 64*65 padded [key][d]
    float* Vs = Ks + 64 * 65;       // 64*64 [key][d]
    float* Ps = Vs + 64 * 64;       // 64*64 [q][key]

    const int qt = blockIdx.x;
    const int h = blockIdx.y;
    const int b = blockIdx.z;
    const int kvh = h / NREP;
    const int tid = threadIdx.x;
    const int warp = tid >> 5;
    const int lane = tid & 31;

    const float* Qbase = Q + (((size_t)b * NH + h) * S + (size_t)qt * 64) * HD;
    const float* Kbase = K + (((size_t)b * NKV + kvh) * S) * HD;
    const float* Vbase = V + (((size_t)b * NKV + kvh) * S) * HD;

#pragma unroll
    for (int i = tid; i < 64 * 64; i += 256) Qs[i] = Qbase[i];

    float m[8], l[8], acc0[8], acc1[8];
#pragma unroll
    for (int i = 0; i < 8; i++) { m[i] = -1e30f; l[i] = 0.f; acc0[i] = 0.f; acc1[i] = 0.f; }

    const float scale = 0.125f;   // 1/sqrt(64)

    for (int kt = 0; kt <= qt; kt++) {
        __syncthreads();
#pragma unroll
        for (int i = tid; i < 64 * 64; i += 256) {
            int r = i >> 6, d = i & 63;
            float kvr = Kbase[((size_t)kt * 64 + r) * HD + d];
            Ks[r * 65 + d] = kvr;
            Vs[i] = Vbase[((size_t)kt * 64 + r) * HD + d];
        }
        __syncthreads();

        const bool diag = (kt == qt);

#pragma unroll
        for (int qi = 0; qi < 8; qi++) {
            const int q = warp * 8 + qi;
            const float* qrow = Qs + q * 64;
            const float* k0 = Ks + lane * 65;
            const float* k1 = Ks + (lane + 32) * 65;
            float s0 = 0.f, s1 = 0.f;
#pragma unroll
            for (int d = 0; d < 64; d++) {
                float qv = qrow[d];
                s0 += qv * k0[d];
                s1 += qv * k1[d];
            }
            s0 *= scale; s1 *= scale;
            if (diag) {
                if (lane > q)      s0 = -1e30f;
                if (lane + 32 > q) s1 = -1e30f;
            }
            float tmax = fmaxf(s0, s1);
#pragma unroll
            for (int off = 16; off; off >>= 1)
                tmax = fmaxf(tmax, __shfl_xor_sync(0xffffffffu, tmax, off));
            float mnew = fmaxf(m[qi], tmax);
            float p0 = __expf(s0 - mnew);
            float p1 = __expf(s1 - mnew);
            if (diag) {  // make masked probs exactly 0 (guard exp of huge-neg)
                if (lane > q)      p0 = 0.f;
                if (lane + 32 > q) p1 = 0.f;
            }
            float ps = p0 + p1;
#pragma unroll
            for (int off = 16; off; off >>= 1)
                ps += __shfl_xor_sync(0xffffffffu, ps, off);
            float corr = __expf(m[qi] - mnew);
            l[qi] = l[qi] * corr + ps;
            m[qi] = mnew;
            acc0[qi] *= corr;
            acc1[qi] *= corr;
            Ps[q * 64 + lane] = p0;
            Ps[q * 64 + lane + 32] = p1;
        }
        __syncwarp();

#pragma unroll
        for (int qi = 0; qi < 8; qi++) {
            const int q = warp * 8 + qi;
            const float* prow = Ps + q * 64;
            float a0 = 0.f, a1 = 0.f;
#pragma unroll
            for (int kk = 0; kk < 64; kk++) {
                float p = prow[kk];
                a0 += p * Vs[kk * 64 + lane];
                a1 += p * Vs[kk * 64 + lane + 32];
            }
            acc0[qi] += a0;
            acc1[qi] += a1;
        }
    }

    // write normalized output to [b, s, h, d]
#pragma unroll
    for (int qi = 0; qi < 8; qi++) {
        const int q = warp * 8 + qi;
        const int sq = qt * 64 + q;
        float invl = 1.f / l[qi];
        float* orow = O + ((size_t)b * S + sq) * HIDDEN + h * HD;
        orow[lane] = acc0[qi] * invl;
        orow[lane + 32] = acc1[qi] * invl;
    }
}

// ---------------- launch ----------------
extern "C" void kernel_launch(void* const* d_in, const int* in_sizes, int n_in,
                              void* d_out, int out_size) {
    const float* hs = (const float*)d_in[0];
    const float* Wq = (const float*)d_in[2];
    const float* bq = (const float*)d_in[3];
    const float* Wk = (const float*)d_in[4];
    const float* bk = (const float*)d_in[5];
    const float* Wv = (const float*)d_in[6];
    const float* bv = (const float*)d_in[7];
    const float* Wo = (const float*)d_in[8];
    float* out = (float*)d_out;

    float *qlin, *klin, *vlin, *q, *k, *v, *attn;
    cudaGetSymbolAddress((void**)&qlin, g_qlin);
    cudaGetSymbolAddress((void**)&klin, g_klin);
    cudaGetSymbolAddress((void**)&vlin, g_vlin);
    cudaGetSymbolAddress((void**)&q, g_q);
    cudaGetSymbolAddress((void**)&k, g_k);
    cudaGetSymbolAddress((void**)&v, g_v);
    cudaGetSymbolAddress((void**)&attn, g_attn);

    static bool attr_set = false;
    if (!attr_set) {
        cudaFuncSetAttribute(attn_kernel, cudaFuncAttributeMaxDynamicSharedMemorySize, ATTN_SMEM);
        attr_set = true;
    }

    // QKV projections
    gemm_xwT<<<dim3(HIDDEN / BN, MTOK / BM), 256>>>(hs, Wq, bq, qlin, MTOK, HIDDEN, HIDDEN);
    gemm_xwT<<<dim3((NKV * HD) / BN, MTOK / BM), 256>>>(hs, Wk, bk, klin, MTOK, NKV * HD, HIDDEN);
    gemm_xwT<<<dim3((NKV * HD) / BN, MTOK / BM), 256>>>(hs, Wv, bv, vlin, MTOK, NKV * HD, HIDDEN);

    // RoPE + layout
    {
        int total = B * S * 18 * 32;
        rope_reshape<<<(total + 255) / 256, 256>>>(qlin, klin, vlin, q, k, v);
    }

    // attention
    attn_kernel<<<dim3(S / 64, NH, B), 256, ATTN_SMEM>>>(q, k, v, attn);

    // output projection
    gemm_xwT<<<dim3(HIDDEN / BN, MTOK / BM), 256>>>(attn, Wo, nullptr, out, MTOK, HIDDEN, HIDDEN);
}